// round 5
// baseline (speedup 1.0000x reference)
#include <cuda_runtime.h>
#include <math.h>

#define N_NODES 100000
#define N_EDGES 50000
#define N_PAIRS 1000000
#define IN_DIM 256
#define OUT_DIM 128
#define HID 32
#define TQ_DIM 64
#define BIGW_ROWS 192
#define NEG_SLOPE 0.2f

// ------------------------- scratch (static device memory) -------------------
__device__ float g_BigW[BIGW_ROWS * IN_DIM];      // [Wv(128) | fc1_a(32) | W3(3) | pad] x 256
__device__ float g_tqW[3 * HID];                  // type_query @ fc1_w[:,256:].T
__device__ float g_V[(size_t)N_NODES * OUT_DIM];  // 51.2 MB
__device__ float g_H[(size_t)N_NODES * 64];       // hidden preacts (32) + S (3) + pad
__device__ float g_A[(size_t)N_NODES * 4];        // gate per node per edge-type
__device__ float g_attn[N_PAIRS];                 // unnormalized ea per pair
__device__ float g_inv_denom[N_EDGES];
__device__ int   g_edge_cnt[N_EDGES];
__device__ int   g_edge_off[N_EDGES + 1];
__device__ int   g_edge_cur[N_EDGES];
__device__ int   g_node_cnt[N_NODES];
__device__ int   g_node_off[N_NODES + 1];
__device__ int   g_node_cur[N_NODES];
__device__ int   g_edge_pairs[N_PAIRS];           // pair id, edge-sorted
__device__ int   g_edge_nodes[N_PAIRS];           // node id payload, edge-sorted
__device__ int   g_node_pairs[N_PAIRS];           // pair id, node-sorted
__device__ int   g_node_edges[N_PAIRS];           // edge id payload, node-sorted

// ------------------------- prep: build fused weight matrix ------------------
__global__ void prep_kernel(const float* __restrict__ Wv,
                            const float* __restrict__ fc1_w,
                            const float* __restrict__ Wq,
                            const float* __restrict__ edge_ctx,
                            const float* __restrict__ type_query) {
    int idx = blockIdx.x * blockDim.x + threadIdx.x;
    const int total = BIGW_ROWS * IN_DIM;
    if (idx < total) {
        int r = idx / IN_DIM, c = idx % IN_DIM;
        float v;
        if (r < 128) {
            v = Wv[r * IN_DIM + c];
        } else if (r < 160) {
            v = fc1_w[(r - 128) * (IN_DIM + TQ_DIM) + c];   // first 256 cols of fc1_w
        } else if (r < 163) {
            int t = r - 160;
            float s = 0.f;
            for (int j = 0; j < OUT_DIM; j++)
                s += edge_ctx[t * OUT_DIM + j] * Wq[j * IN_DIM + c];
            v = s;   // W3 = edge_ctx @ Wq
        } else {
            v = 0.f;
        }
        g_BigW[idx] = v;
    } else if (idx < total + 3 * HID) {
        int e2 = idx - total;
        int t = e2 / HID, j = e2 % HID;
        float s = 0.f;
        for (int d = 0; d < TQ_DIM; d++)
            s += type_query[t * TQ_DIM + d] * fc1_w[j * (IN_DIM + TQ_DIM) + IN_DIM + d];
        g_tqW[t * HID + j] = s;
    }
}

// ------------------------- GEMM V: g_V = x @ Wv.T (BN=128, 8x8/thread) -----
#define BM 128
#define BK 16

__global__ __launch_bounds__(256) void gemm_v(const float* __restrict__ x) {
    __shared__ float As[BK][BM + 4];
    __shared__ float Bs[BK][128 + 4];
    const int row0 = blockIdx.x * BM;
    const float* Bsrc = g_BigW;                   // Wv rows 0..127
    const int tid = threadIdx.x;
    const int tcol = tid & 15;   // n0 = tcol*8
    const int trow = tid >> 4;   // m0 = trow*8

    const int ar0 = (tid) >> 2,        ac0 = (tid) & 3;
    const int ar1 = (tid + 256) >> 2,  ac1 = (tid + 256) & 3;
    const int gra0 = row0 + ar0, gra1 = row0 + ar1;

    float4 pa0, pa1, pb0, pb1;
    pa0 = make_float4(0.f, 0.f, 0.f, 0.f);
    pa1 = pa0;
    if (gra0 < N_NODES) pa0 = *(const float4*)(x + (size_t)gra0 * IN_DIM + ac0 * 4);
    if (gra1 < N_NODES) pa1 = *(const float4*)(x + (size_t)gra1 * IN_DIM + ac1 * 4);
    pb0 = *(const float4*)(Bsrc + (size_t)ar0 * IN_DIM + ac0 * 4);
    pb1 = *(const float4*)(Bsrc + (size_t)ar1 * IN_DIM + ac1 * 4);

    float acc[8][8];
#pragma unroll
    for (int i = 0; i < 8; i++)
#pragma unroll
        for (int j = 0; j < 8; j++) acc[i][j] = 0.f;

    for (int k0 = 0; k0 < IN_DIM; k0 += BK) {
        As[ac0 * 4 + 0][ar0] = pa0.x; As[ac0 * 4 + 1][ar0] = pa0.y;
        As[ac0 * 4 + 2][ar0] = pa0.z; As[ac0 * 4 + 3][ar0] = pa0.w;
        As[ac1 * 4 + 0][ar1] = pa1.x; As[ac1 * 4 + 1][ar1] = pa1.y;
        As[ac1 * 4 + 2][ar1] = pa1.z; As[ac1 * 4 + 3][ar1] = pa1.w;
        Bs[ac0 * 4 + 0][ar0] = pb0.x; Bs[ac0 * 4 + 1][ar0] = pb0.y;
        Bs[ac0 * 4 + 2][ar0] = pb0.z; Bs[ac0 * 4 + 3][ar0] = pb0.w;
        Bs[ac1 * 4 + 0][ar1] = pb1.x; Bs[ac1 * 4 + 1][ar1] = pb1.y;
        Bs[ac1 * 4 + 2][ar1] = pb1.z; Bs[ac1 * 4 + 3][ar1] = pb1.w;
        __syncthreads();

        int kn = k0 + BK;
        if (kn < IN_DIM) {
            pa0 = make_float4(0.f, 0.f, 0.f, 0.f);
            pa1 = pa0;
            if (gra0 < N_NODES) pa0 = *(const float4*)(x + (size_t)gra0 * IN_DIM + kn + ac0 * 4);
            if (gra1 < N_NODES) pa1 = *(const float4*)(x + (size_t)gra1 * IN_DIM + kn + ac1 * 4);
            pb0 = *(const float4*)(Bsrc + (size_t)ar0 * IN_DIM + kn + ac0 * 4);
            pb1 = *(const float4*)(Bsrc + (size_t)ar1 * IN_DIM + kn + ac1 * 4);
        }

#pragma unroll
        for (int k = 0; k < BK; k++) {
            float a[8], b[8];
#pragma unroll
            for (int i = 0; i < 8; i++) a[i] = As[k][trow * 8 + i];
#pragma unroll
            for (int j = 0; j < 8; j++) b[j] = Bs[k][tcol * 8 + j];
#pragma unroll
            for (int i = 0; i < 8; i++)
#pragma unroll
                for (int j = 0; j < 8; j++) acc[i][j] += a[i] * b[j];
        }
        __syncthreads();
    }

#pragma unroll
    for (int i = 0; i < 8; i++) {
        int gr = row0 + trow * 8 + i;
        if (gr >= N_NODES) continue;
        float* dst = g_V + (size_t)gr * OUT_DIM + tcol * 8;
        *(float4*)(dst + 0) = make_float4(acc[i][0], acc[i][1], acc[i][2], acc[i][3]);
        *(float4*)(dst + 4) = make_float4(acc[i][4], acc[i][5], acc[i][6], acc[i][7]);
    }
}

// ------------------------- GEMM H: g_H = x @ [fc1_a|W3].T (BN=64) ----------
__global__ __launch_bounds__(256) void gemm_h(const float* __restrict__ x) {
    __shared__ float As[BK][BM + 4];
    __shared__ float Bs[BK][64 + 4];
    const int row0 = blockIdx.x * BM;
    const float* Bsrc = g_BigW + (size_t)128 * IN_DIM;
    const int tid = threadIdx.x;
    const int tcol = tid & 15;   // n0 = tcol*4
    const int trow = tid >> 4;   // m0 = trow*8

    const int ar0 = (tid) >> 2,        ac0 = (tid) & 3;
    const int ar1 = (tid + 256) >> 2,  ac1 = (tid + 256) & 3;
    const int gra0 = row0 + ar0, gra1 = row0 + ar1;
    const int bn = tid >> 2, bc = tid & 3;

    float4 pa0, pa1, pb0;
    pa0 = make_float4(0.f, 0.f, 0.f, 0.f);
    pa1 = pa0;
    if (gra0 < N_NODES) pa0 = *(const float4*)(x + (size_t)gra0 * IN_DIM + ac0 * 4);
    if (gra1 < N_NODES) pa1 = *(const float4*)(x + (size_t)gra1 * IN_DIM + ac1 * 4);
    pb0 = *(const float4*)(Bsrc + (size_t)bn * IN_DIM + bc * 4);

    float acc[8][4];
#pragma unroll
    for (int i = 0; i < 8; i++)
#pragma unroll
        for (int j = 0; j < 4; j++) acc[i][j] = 0.f;

    for (int k0 = 0; k0 < IN_DIM; k0 += BK) {
        As[ac0 * 4 + 0][ar0] = pa0.x; As[ac0 * 4 + 1][ar0] = pa0.y;
        As[ac0 * 4 + 2][ar0] = pa0.z; As[ac0 * 4 + 3][ar0] = pa0.w;
        As[ac1 * 4 + 0][ar1] = pa1.x; As[ac1 * 4 + 1][ar1] = pa1.y;
        As[ac1 * 4 + 2][ar1] = pa1.z; As[ac1 * 4 + 3][ar1] = pa1.w;
        Bs[bc * 4 + 0][bn] = pb0.x; Bs[bc * 4 + 1][bn] = pb0.y;
        Bs[bc * 4 + 2][bn] = pb0.z; Bs[bc * 4 + 3][bn] = pb0.w;
        __syncthreads();

        int kn = k0 + BK;
        if (kn < IN_DIM) {
            pa0 = make_float4(0.f, 0.f, 0.f, 0.f);
            pa1 = pa0;
            if (gra0 < N_NODES) pa0 = *(const float4*)(x + (size_t)gra0 * IN_DIM + kn + ac0 * 4);
            if (gra1 < N_NODES) pa1 = *(const float4*)(x + (size_t)gra1 * IN_DIM + kn + ac1 * 4);
            pb0 = *(const float4*)(Bsrc + (size_t)bn * IN_DIM + kn + bc * 4);
        }

#pragma unroll
        for (int k = 0; k < BK; k++) {
            float a[8], b[4];
#pragma unroll
            for (int i = 0; i < 8; i++) a[i] = As[k][trow * 8 + i];
#pragma unroll
            for (int j = 0; j < 4; j++) b[j] = Bs[k][tcol * 4 + j];
#pragma unroll
            for (int i = 0; i < 8; i++)
#pragma unroll
                for (int j = 0; j < 4; j++) acc[i][j] += a[i] * b[j];
        }
        __syncthreads();
    }

#pragma unroll
    for (int i = 0; i < 8; i++) {
        int gr = row0 + trow * 8 + i;
        if (gr >= N_NODES) continue;
        *(float4*)(g_H + (size_t)gr * 64 + tcol * 4) =
            make_float4(acc[i][0], acc[i][1], acc[i][2], acc[i][3]);
    }
}

// ------------------------- per-node gates: A[n][t] --------------------------
__global__ void post_kernel(const int* __restrict__ node_types,
                            const float* __restrict__ fc1_b,
                            const float* __restrict__ fc2_w,
                            const float* __restrict__ fc2_b) {
    int warp = (blockIdx.x * blockDim.x + threadIdx.x) >> 5;
    int lane = threadIdx.x & 31;
    if (warp >= N_NODES) return;
    int n = warp;
    int t = node_types[n];
    float h = tanhf(g_H[(size_t)n * 64 + lane] + g_tqW[t * HID + lane] + fc1_b[lane]);
    float c = h * fc2_w[lane];
#pragma unroll
    for (int d = 16; d; d >>= 1) c += __shfl_xor_sync(0xffffffffu, c, d);
    float at = 1.f / (1.f + __expf(-(c + fc2_b[0])));
    if (lane < 3) {
        float s = g_H[(size_t)n * 64 + 32 + lane];
        s = s >= 0.f ? s : NEG_SLOPE * s;
        g_A[(size_t)n * 4 + lane] = s * at;
    }
}

// ------------------------- CSR build ----------------------------------------
__global__ void zero_kernel() {
    int i = blockIdx.x * blockDim.x + threadIdx.x;
    if (i < N_EDGES) g_edge_cnt[i] = 0;
    if (i < N_NODES) g_node_cnt[i] = 0;
}

__global__ void hist_kernel(const int* __restrict__ edge_idx,
                            const int* __restrict__ node_idx) {
    int stride = gridDim.x * blockDim.x;
    for (int p = blockIdx.x * blockDim.x + threadIdx.x; p < N_PAIRS; p += stride) {
        int e = edge_idx[p];
        int n = node_idx[p];
        atomicAdd(&g_edge_cnt[e], 1);
        atomicAdd(&g_node_cnt[n], 1);
    }
}

__global__ void scan_kernel() {
    int n;
    int *cnt, *off, *cur;
    if (blockIdx.x == 0) { n = N_EDGES; cnt = g_edge_cnt; off = g_edge_off; cur = g_edge_cur; }
    else                 { n = N_NODES; cnt = g_node_cnt; off = g_node_off; cur = g_node_cur; }
    __shared__ int wsum[32];
    __shared__ int s_total;
    __shared__ int s_carry;
    int tid = threadIdx.x, lane = tid & 31, wid = tid >> 5;
    if (tid == 0) s_carry = 0;
    __syncthreads();
    for (int base = 0; base < n; base += 1024) {
        int i = base + tid;
        int v = (i < n) ? cnt[i] : 0;
        int incl = v;
#pragma unroll
        for (int d = 1; d < 32; d <<= 1) {
            int y = __shfl_up_sync(0xffffffffu, incl, d);
            if (lane >= d) incl += y;
        }
        if (lane == 31) wsum[wid] = incl;
        __syncthreads();
        if (wid == 0) {
            int s = wsum[lane];
            int si = s;
#pragma unroll
            for (int d = 1; d < 32; d <<= 1) {
                int y = __shfl_up_sync(0xffffffffu, si, d);
                if (lane >= d) si += y;
            }
            wsum[lane] = si - s;
            if (lane == 31) s_total = si;
        }
        __syncthreads();
        int excl = s_carry + wsum[wid] + incl - v;
        if (i < n) { off[i] = excl; cur[i] = excl; }
        __syncthreads();
        if (tid == 0) s_carry += s_total;
        __syncthreads();
    }
    if (threadIdx.x == 0) off[n] = s_carry;
}

__global__ void scatter_kernel(const int* __restrict__ edge_idx,
                               const int* __restrict__ node_idx) {
    int stride = gridDim.x * blockDim.x;
    for (int p = blockIdx.x * blockDim.x + threadIdx.x; p < N_PAIRS; p += stride) {
        int e = edge_idx[p];
        int n = node_idx[p];
        int pos = atomicAdd(&g_edge_cur[e], 1);
        g_edge_pairs[pos] = p;
        g_edge_nodes[pos] = n;          // payload: avoids random node_idx[p] later
        int pos2 = atomicAdd(&g_node_cur[n], 1);
        g_node_pairs[pos2] = p;
        g_node_edges[pos2] = e;         // payload: avoids random edge_idx[p] later
    }
}

// ------------- segment softmax + edge aggregation (1 warp / edge) ----------
__global__ void edge_kernel(const int* __restrict__ edge_type,
                            float* __restrict__ edge_feat) {
    int warp = (blockIdx.x * blockDim.x + threadIdx.x) >> 5;
    int lane = threadIdx.x & 31;
    if (warp >= N_EDGES) return;
    int e = warp;
    int start = g_edge_off[e], end = g_edge_off[e + 1];
    int cnt = end - start;
    int et = edge_type[e];
    const float4* Vb = (const float4*)g_V;
    float4 acc = make_float4(0.f, 0.f, 0.f, 0.f);
    float inv;

    if (cnt <= 32) {
        // ---- fast path: whole segment fits in one register per lane ----
        bool valid = lane < cnt;
        int p = 0, n = 0;
        float a = -3.4e38f;
        if (valid) {
            p = g_edge_pairs[start + lane];
            n = g_edge_nodes[start + lane];
            a = g_A[(size_t)n * 4 + et];
        }
        float m = a;
#pragma unroll
        for (int d = 16; d; d >>= 1) m = fmaxf(m, __shfl_xor_sync(0xffffffffu, m, d));
        float ea = valid ? __expf(a - m) : 0.f;
        float s = ea;
#pragma unroll
        for (int d = 16; d; d >>= 1) s += __shfl_xor_sync(0xffffffffu, s, d);
        inv = (s > 0.f) ? 1.f / s : 0.f;
        if (valid) g_attn[p] = ea;      // node phase needs unnormalized ea
        // pass 3 via shuffle broadcast: no memory re-reads
        for (int j = 0; j < cnt; j++) {
            float w = __shfl_sync(0xffffffffu, ea, j);
            int  nn = __shfl_sync(0xffffffffu, n, j);
            float4 v = Vb[(size_t)nn * 32 + lane];
            acc.x += w * v.x; acc.y += w * v.y; acc.z += w * v.z; acc.w += w * v.w;
        }
    } else {
        // ---- slow path: multi-chunk segment ----
        float m = -3.4e38f;
        for (int i = start + lane; i < end; i += 32) {
            int n = g_edge_nodes[i];
            float a = g_A[(size_t)n * 4 + et];
            g_attn[g_edge_pairs[i]] = a;    // stage raw alpha
            m = fmaxf(m, a);
        }
#pragma unroll
        for (int d = 16; d; d >>= 1) m = fmaxf(m, __shfl_xor_sync(0xffffffffu, m, d));
        float s = 0.f;
        for (int i = start + lane; i < end; i += 32) {
            int p = g_edge_pairs[i];
            float ea = __expf(g_attn[p] - m);
            g_attn[p] = ea;
            s += ea;
        }
#pragma unroll
        for (int d = 16; d; d >>= 1) s += __shfl_xor_sync(0xffffffffu, s, d);
        inv = (s > 0.f) ? 1.f / s : 0.f;
        __syncwarp();
        for (int i = start; i < end; i++) {
            float w = g_attn[g_edge_pairs[i]];  // uniform broadcast load
            int n = g_edge_nodes[i];            // sequential
            float4 v = Vb[(size_t)n * 32 + lane];
            acc.x += w * v.x; acc.y += w * v.y; acc.z += w * v.z; acc.w += w * v.w;
        }
    }
    if (lane == 0) g_inv_denom[e] = inv;
    float4 r = make_float4(acc.x * inv, acc.y * inv, acc.z * inv, acc.w * inv);
    ((float4*)edge_feat)[(size_t)e * 32 + lane] = r;
}

// ------------- node aggregation (1 warp / node, pure gather) ----------------
__global__ void node_kernel(float* __restrict__ node_feat,
                            const float* __restrict__ edge_feat) {
    int warp = (blockIdx.x * blockDim.x + threadIdx.x) >> 5;
    int lane = threadIdx.x & 31;
    if (warp >= N_NODES) return;
    int n = warp;
    int start = g_node_off[n], end = g_node_off[n + 1];
    float4 acc = make_float4(0.f, 0.f, 0.f, 0.f);
    const float4* EF = (const float4*)edge_feat;
    for (int i = start; i < end; i++) {
        int p = g_node_pairs[i];                 // sequential
        int e = g_node_edges[i];                 // sequential
        float w = g_attn[p] * g_inv_denom[e];    // 2 uniform L2 loads
        float4 ef = EF[(size_t)e * 32 + lane];
        acc.x += w * ef.x; acc.y += w * ef.y; acc.z += w * ef.z; acc.w += w * ef.w;
    }
    ((float4*)node_feat)[(size_t)n * 32 + lane] = acc;
}

// ------------------------- launch -------------------------------------------
extern "C" void kernel_launch(void* const* d_in, const int* in_sizes, int n_in,
                              void* d_out, int out_size) {
    const float* x          = (const float*)d_in[0];
    const int*   node_types = (const int*)  d_in[1];
    const int*   edge_type  = (const int*)  d_in[2];
    const int*   node_idx   = (const int*)  d_in[3];
    const int*   edge_idx   = (const int*)  d_in[4];
    const float* type_query = (const float*)d_in[5];
    const float* fc1_w      = (const float*)d_in[6];
    const float* fc1_b      = (const float*)d_in[7];
    const float* fc2_w      = (const float*)d_in[8];
    const float* fc2_b      = (const float*)d_in[9];
    const float* Wq         = (const float*)d_in[10];
    const float* Wv         = (const float*)d_in[11];
    const float* edge_ctx   = (const float*)d_in[12];

    float* node_feat = (float*)d_out;                              // (N, 128)
    float* edge_feat = (float*)d_out + (size_t)N_NODES * OUT_DIM;  // (E, 128)

    prep_kernel<<<(BIGW_ROWS * IN_DIM + 3 * HID + 255) / 256, 256>>>(
        Wv, fc1_w, Wq, edge_ctx, type_query);

    int gblocks = (N_NODES + BM - 1) / BM;
    gemm_v<<<gblocks, 256>>>(x);
    gemm_h<<<gblocks, 256>>>(x);

    post_kernel<<<(N_NODES * 32 + 255) / 256, 256>>>(node_types, fc1_b, fc2_w, fc2_b);

    zero_kernel<<<(N_NODES + 255) / 256, 256>>>();
    hist_kernel<<<1024, 256>>>(edge_idx, node_idx);
    scan_kernel<<<2, 1024>>>();
    scatter_kernel<<<1024, 256>>>(edge_idx, node_idx);

    edge_kernel<<<(N_EDGES * 32 + 255) / 256, 256>>>(edge_type, edge_feat);
    node_kernel<<<(N_NODES * 32 + 255) / 256, 256>>>(node_feat, edge_feat);
}

// round 10
// speedup vs baseline: 1.5037x; 1.5037x over previous
#include <cuda_runtime.h>
#include <cuda_bf16.h>
#include <math.h>
#include <stdint.h>

#define N_NODES 100000
#define N_EDGES 50000
#define N_PAIRS 1000000
#define IN_DIM 256
#define OUT_DIM 128
#define HID 32
#define TQ_DIM 64
#define BIGW_ROWS 192
#define NEG_SLOPE 0.2f

// ------------------------- scratch (static device memory) -------------------
__device__ float g_BigW[BIGW_ROWS * IN_DIM];      // [Wv(128) | fc1_a(32) | W3(3) | pad] x 256
__device__ float g_tqW[3 * HID];
__device__ float g_V[(size_t)N_NODES * OUT_DIM];
__device__ float g_H[(size_t)N_NODES * 64];
__device__ float g_A[(size_t)N_NODES * 4];
__device__ float g_attn[N_PAIRS];
__device__ float g_inv_denom[N_EDGES];
__device__ int   g_edge_cnt[N_EDGES];
__device__ int   g_edge_off[N_EDGES + 1];
__device__ int   g_edge_cur[N_EDGES];
__device__ int   g_node_cnt[N_NODES];
__device__ int   g_node_off[N_NODES + 1];
__device__ int   g_node_cur[N_NODES];
__device__ int   g_edge_pairs[N_PAIRS];
__device__ int   g_edge_nodes[N_PAIRS];
__device__ int   g_node_pairs[N_PAIRS];
__device__ int   g_node_edges[N_PAIRS];
// bf16 hi/lo weights, plain row-major [192][256]
__device__ __nv_bfloat16 g_Whi[BIGW_ROWS * IN_DIM];
__device__ __nv_bfloat16 g_Wlo[BIGW_ROWS * IN_DIM];

// ------------------------- prep1: fused fp32 weights -------------------------
__global__ void prep_kernel(const float* __restrict__ Wv,
                            const float* __restrict__ fc1_w,
                            const float* __restrict__ Wq,
                            const float* __restrict__ edge_ctx,
                            const float* __restrict__ type_query) {
    int idx = blockIdx.x * blockDim.x + threadIdx.x;
    const int total = BIGW_ROWS * IN_DIM;
    if (idx < total) {
        int r = idx / IN_DIM, c = idx % IN_DIM;
        float v;
        if (r < 128) {
            v = Wv[r * IN_DIM + c];
        } else if (r < 160) {
            v = fc1_w[(r - 128) * (IN_DIM + TQ_DIM) + c];
        } else if (r < 163) {
            int t = r - 160;
            float s = 0.f;
            for (int j = 0; j < OUT_DIM; j++)
                s += edge_ctx[t * OUT_DIM + j] * Wq[j * IN_DIM + c];
            v = s;
        } else {
            v = 0.f;
        }
        g_BigW[idx] = v;
    } else if (idx < total + 3 * HID) {
        int e2 = idx - total;
        int t = e2 / HID, j = e2 % HID;
        float s = 0.f;
        for (int d = 0; d < TQ_DIM; d++)
            s += type_query[t * TQ_DIM + d] * fc1_w[j * (IN_DIM + TQ_DIM) + IN_DIM + d];
        g_tqW[t * HID + j] = s;
    }
}

// ------------------------- prep2: bf16 hi/lo weights -------------------------
__global__ void prep2_kernel() {
    int idx = blockIdx.x * blockDim.x + threadIdx.x;
    if (idx >= BIGW_ROWS * IN_DIM) return;
    float w = g_BigW[idx];
    __nv_bfloat16 hi = __float2bfloat16(w);
    __nv_bfloat16 lo = __float2bfloat16(w - __bfloat162float(hi));
    g_Whi[idx] = hi;
    g_Wlo[idx] = lo;
}

// ------------------------- HMMA GEMM: [V | H] = x @ BigW.T ------------------
// mma.sync m16n8k16 bf16, split-bf16 3-term: D = Ah*Bh + Al*Bh + Ah*Bl.
// CTA tile 128x64, 8 warps (4M x 2N), warp tile 32x32; K chunks of 32.
// grid.y: 0 -> V[:,0:64), 1 -> V[:,64:128), 2 -> H (BigW rows 128-191).
#define GLDA 40   // smem row stride in halfs (32 + 8 pad)

__device__ __forceinline__ void mma16816(float* c, const uint32_t* a, const uint32_t* b) {
    asm volatile(
        "mma.sync.aligned.m16n8k16.row.col.f32.bf16.bf16.f32 "
        "{%0,%1,%2,%3}, {%4,%5,%6,%7}, {%8,%9}, {%0,%1,%2,%3};"
        : "+f"(c[0]), "+f"(c[1]), "+f"(c[2]), "+f"(c[3])
        : "r"(a[0]), "r"(a[1]), "r"(a[2]), "r"(a[3]), "r"(b[0]), "r"(b[1]));
}

__global__ __launch_bounds__(256) void hmma_gemm(const float* __restrict__ x) {
    __shared__ __nv_bfloat16 Ah[128 * GLDA];
    __shared__ __nv_bfloat16 Al[128 * GLDA];
    __shared__ __nv_bfloat16 Bh[64 * GLDA];
    __shared__ __nv_bfloat16 Bl[64 * GLDA];

    const int tid = threadIdx.x;
    const int wid = tid >> 5, lane = tid & 31;
    const int g = lane >> 2, t = lane & 3;            // mma group / thread-in-group
    const int warp_m = wid >> 1, warp_n = wid & 1;    // 4 x 2 warp grid
    const int row0 = blockIdx.x * 128;
    const int by = blockIdx.y;
    const __nv_bfloat16* Whi = g_Whi + (size_t)by * 64 * IN_DIM;
    const __nv_bfloat16* Wlo = g_Wlo + (size_t)by * 64 * IN_DIM;

    float acc[2][4][4];
#pragma unroll
    for (int mt = 0; mt < 2; mt++)
#pragma unroll
        for (int nt = 0; nt < 4; nt++)
#pragma unroll
            for (int q = 0; q < 4; q++) acc[mt][nt][q] = 0.f;

    for (int k0 = 0; k0 < IN_DIM; k0 += 32) {
        // ---- A: 128 rows x 32 k-cols fp32 -> bf16 hi/lo ----
#pragma unroll
        for (int i = 0; i < 4; i++) {
            int idx = tid + i * 256;        // 0..1023
            int r = idx >> 3, c4 = idx & 7; // row, float4 index (col = c4*4)
            float4 v = make_float4(0.f, 0.f, 0.f, 0.f);
            int gr = row0 + r;
            if (gr < N_NODES)
                v = *(const float4*)(x + (size_t)gr * IN_DIM + k0 + c4 * 4);
            __nv_bfloat16 h0 = __float2bfloat16(v.x), h1 = __float2bfloat16(v.y);
            __nv_bfloat16 h2 = __float2bfloat16(v.z), h3 = __float2bfloat16(v.w);
            __nv_bfloat16 l0 = __float2bfloat16(v.x - __bfloat162float(h0));
            __nv_bfloat16 l1 = __float2bfloat16(v.y - __bfloat162float(h1));
            __nv_bfloat16 l2 = __float2bfloat16(v.z - __bfloat162float(h2));
            __nv_bfloat16 l3 = __float2bfloat16(v.w - __bfloat162float(h3));
            int base = r * GLDA + c4 * 4;
            __nv_bfloat162 p;
            p.x = h0; p.y = h1; *(__nv_bfloat162*)&Ah[base]     = p;
            p.x = h2; p.y = h3; *(__nv_bfloat162*)&Ah[base + 2] = p;
            p.x = l0; p.y = l1; *(__nv_bfloat162*)&Al[base]     = p;
            p.x = l2; p.y = l3; *(__nv_bfloat162*)&Al[base + 2] = p;
        }
        // ---- B: 64 rows x 32 k-cols bf16, uint4 copies ----
        {
            int r = tid >> 2, c8 = tid & 3;  // 64 rows x 4 uint4/row = 256
            const uint4* sh = (const uint4*)(Whi + (size_t)r * IN_DIM + k0 + c8 * 8);
            const uint4* sl = (const uint4*)(Wlo + (size_t)r * IN_DIM + k0 + c8 * 8);
            *(uint4*)&Bh[r * GLDA + c8 * 8] = *sh;
            *(uint4*)&Bl[r * GLDA + c8 * 8] = *sl;
        }
        __syncthreads();

#pragma unroll
        for (int ks = 0; ks < 2; ks++) {
            int kb = ks * 16;
            uint32_t ah[2][4], al[2][4], bh[4][2], bl[4][2];
#pragma unroll
            for (int mt = 0; mt < 2; mt++) {
                int rb = warp_m * 32 + mt * 16;
                ah[mt][0] = *(uint32_t*)&Ah[(rb + g) * GLDA + kb + 2 * t];
                ah[mt][1] = *(uint32_t*)&Ah[(rb + g + 8) * GLDA + kb + 2 * t];
                ah[mt][2] = *(uint32_t*)&Ah[(rb + g) * GLDA + kb + 2 * t + 8];
                ah[mt][3] = *(uint32_t*)&Ah[(rb + g + 8) * GLDA + kb + 2 * t + 8];
                al[mt][0] = *(uint32_t*)&Al[(rb + g) * GLDA + kb + 2 * t];
                al[mt][1] = *(uint32_t*)&Al[(rb + g + 8) * GLDA + kb + 2 * t];
                al[mt][2] = *(uint32_t*)&Al[(rb + g) * GLDA + kb + 2 * t + 8];
                al[mt][3] = *(uint32_t*)&Al[(rb + g + 8) * GLDA + kb + 2 * t + 8];
            }
#pragma unroll
            for (int nt = 0; nt < 4; nt++) {
                int nb = warp_n * 32 + nt * 8;
                bh[nt][0] = *(uint32_t*)&Bh[(nb + g) * GLDA + kb + 2 * t];
                bh[nt][1] = *(uint32_t*)&Bh[(nb + g) * GLDA + kb + 2 * t + 8];
                bl[nt][0] = *(uint32_t*)&Bl[(nb + g) * GLDA + kb + 2 * t];
                bl[nt][1] = *(uint32_t*)&Bl[(nb + g) * GLDA + kb + 2 * t + 8];
            }
#pragma unroll
            for (int mt = 0; mt < 2; mt++)
#pragma unroll
                for (int nt = 0; nt < 4; nt++) {
                    mma16816(acc[mt][nt], ah[mt], bh[nt]);
                    mma16816(acc[mt][nt], al[mt], bh[nt]);
                    mma16816(acc[mt][nt], ah[mt], bl[nt]);
                }
        }
        __syncthreads();
    }

    // ---- epilogue: thread holds rows (g, g+8) cols (2t, 2t+1) per tile ----
#pragma unroll
    for (int mt = 0; mt < 2; mt++) {
#pragma unroll
        for (int half = 0; half < 2; half++) {
            int lr = warp_m * 32 + mt * 16 + g + half * 8;
            int gr = row0 + lr;
            if (gr >= N_NODES) continue;
#pragma unroll
            for (int nt = 0; nt < 4; nt++) {
                int col = warp_n * 32 + nt * 8 + 2 * t;
                float2 v;
                v.x = acc[mt][nt][half * 2 + 0];
                v.y = acc[mt][nt][half * 2 + 1];
                if (by < 2)
                    *(float2*)(g_V + (size_t)gr * OUT_DIM + by * 64 + col) = v;
                else
                    *(float2*)(g_H + (size_t)gr * 64 + col) = v;
            }
        }
    }
}

// ------------------------- per-node gates: A[n][t] --------------------------
__global__ void post_kernel(const int* __restrict__ node_types,
                            const float* __restrict__ fc1_b,
                            const float* __restrict__ fc2_w,
                            const float* __restrict__ fc2_b) {
    int warp = (blockIdx.x * blockDim.x + threadIdx.x) >> 5;
    int lane = threadIdx.x & 31;
    if (warp >= N_NODES) return;
    int n = warp;
    int t = node_types[n];
    float h = tanhf(g_H[(size_t)n * 64 + lane] + g_tqW[t * HID + lane] + fc1_b[lane]);
    float c = h * fc2_w[lane];
#pragma unroll
    for (int d = 16; d; d >>= 1) c += __shfl_xor_sync(0xffffffffu, c, d);
    float at = 1.f / (1.f + __expf(-(c + fc2_b[0])));
    if (lane < 3) {
        float s = g_H[(size_t)n * 64 + 32 + lane];
        s = s >= 0.f ? s : NEG_SLOPE * s;
        g_A[(size_t)n * 4 + lane] = s * at;
    }
}

// ------------------------- CSR build ----------------------------------------
__global__ void zero_kernel() {
    int i = blockIdx.x * blockDim.x + threadIdx.x;
    if (i < N_EDGES) g_edge_cnt[i] = 0;
    if (i < N_NODES) g_node_cnt[i] = 0;
}

__global__ void hist_kernel(const int* __restrict__ edge_idx,
                            const int* __restrict__ node_idx) {
    int stride = gridDim.x * blockDim.x;
    for (int p = blockIdx.x * blockDim.x + threadIdx.x; p < N_PAIRS; p += stride) {
        int e = edge_idx[p];
        int n = node_idx[p];
        atomicAdd(&g_edge_cnt[e], 1);
        atomicAdd(&g_node_cnt[n], 1);
    }
}

__global__ void scan_kernel() {
    int n;
    int *cnt, *off, *cur;
    if (blockIdx.x == 0) { n = N_EDGES; cnt = g_edge_cnt; off = g_edge_off; cur = g_edge_cur; }
    else                 { n = N_NODES; cnt = g_node_cnt; off = g_node_off; cur = g_node_cur; }
    __shared__ int wsum[32];
    __shared__ int s_total;
    __shared__ int s_carry;
    int tid = threadIdx.x, lane = tid & 31, wid = tid >> 5;
    if (tid == 0) s_carry = 0;
    __syncthreads();
    for (int base = 0; base < n; base += 1024) {
        int i = base + tid;
        int v = (i < n) ? cnt[i] : 0;
        int incl = v;
#pragma unroll
        for (int d = 1; d < 32; d <<= 1) {
            int y = __shfl_up_sync(0xffffffffu, incl, d);
            if (lane >= d) incl += y;
        }
        if (lane == 31) wsum[wid] = incl;
        __syncthreads();
        if (wid == 0) {
            int s = wsum[lane];
            int si = s;
#pragma unroll
            for (int d = 1; d < 32; d <<= 1) {
                int y = __shfl_up_sync(0xffffffffu, si, d);
                if (lane >= d) si += y;
            }
            wsum[lane] = si - s;
            if (lane == 31) s_total = si;
        }
        __syncthreads();
        int excl = s_carry + wsum[wid] + incl - v;
        if (i < n) { off[i] = excl; cur[i] = excl; }
        __syncthreads();
        if (tid == 0) s_carry += s_total;
        __syncthreads();
    }
    if (threadIdx.x == 0) off[n] = s_carry;
}

__global__ void scatter_kernel(const int* __restrict__ edge_idx,
                               const int* __restrict__ node_idx) {
    int stride = gridDim.x * blockDim.x;
    for (int p = blockIdx.x * blockDim.x + threadIdx.x; p < N_PAIRS; p += stride) {
        int e = edge_idx[p];
        int n = node_idx[p];
        int pos = atomicAdd(&g_edge_cur[e], 1);
        g_edge_pairs[pos] = p;
        g_edge_nodes[pos] = n;
        int pos2 = atomicAdd(&g_node_cur[n], 1);
        g_node_pairs[pos2] = p;
        g_node_edges[pos2] = e;
    }
}

// ------------- segment softmax + edge aggregation (1 warp / edge) ----------
__global__ void edge_kernel(const int* __restrict__ edge_type,
                            float* __restrict__ edge_feat) {
    int warp = (blockIdx.x * blockDim.x + threadIdx.x) >> 5;
    int lane = threadIdx.x & 31;
    if (warp >= N_EDGES) return;
    int e = warp;
    int start = g_edge_off[e], end = g_edge_off[e + 1];
    int cnt = end - start;
    int et = edge_type[e];
    const float4* Vb = (const float4*)g_V;
    float4 acc = make_float4(0.f, 0.f, 0.f, 0.f);
    float inv;

    if (cnt <= 32) {
        bool valid = lane < cnt;
        int p = 0, n = 0;
        float a = -3.4e38f;
        if (valid) {
            p = g_edge_pairs[start + lane];
            n = g_edge_nodes[start + lane];
            a = g_A[(size_t)n * 4 + et];
        }
        float m = a;
#pragma unroll
        for (int d = 16; d; d >>= 1) m = fmaxf(m, __shfl_xor_sync(0xffffffffu, m, d));
        float ea = valid ? __expf(a - m) : 0.f;
        float s = ea;
#pragma unroll
        for (int d = 16; d; d >>= 1) s += __shfl_xor_sync(0xffffffffu, s, d);
        inv = (s > 0.f) ? 1.f / s : 0.f;
        if (valid) g_attn[p] = ea;
        for (int j = 0; j < cnt; j++) {
            float w = __shfl_sync(0xffffffffu, ea, j);
            int  nn = __shfl_sync(0xffffffffu, n, j);
            float4 v = Vb[(size_t)nn * 32 + lane];
            acc.x += w * v.x; acc.y += w * v.y; acc.z += w * v.z; acc.w += w * v.w;
        }
    } else {
        float m = -3.4e38f;
        for (int i = start + lane; i < end; i += 32) {
            int n = g_edge_nodes[i];
            float a = g_A[(size_t)n * 4 + et];
            g_attn[g_edge_pairs[i]] = a;
            m = fmaxf(m, a);
        }
#pragma unroll
        for (int d = 16; d; d >>= 1) m = fmaxf(m, __shfl_xor_sync(0xffffffffu, m, d));
        float s = 0.f;
        for (int i = start + lane; i < end; i += 32) {
            int p = g_edge_pairs[i];
            float ea = __expf(g_attn[p] - m);
            g_attn[p] = ea;
            s += ea;
        }
#pragma unroll
        for (int d = 16; d; d >>= 1) s += __shfl_xor_sync(0xffffffffu, s, d);
        inv = (s > 0.f) ? 1.f / s : 0.f;
        __syncwarp();
        for (int i = start; i < end; i++) {
            float w = g_attn[g_edge_pairs[i]];
            int n = g_edge_nodes[i];
            float4 v = Vb[(size_t)n * 32 + lane];
            acc.x += w * v.x; acc.y += w * v.y; acc.z += w * v.z; acc.w += w * v.w;
        }
    }
    if (lane == 0) g_inv_denom[e] = inv;
    float4 r = make_float4(acc.x * inv, acc.y * inv, acc.z * inv, acc.w * inv);
    ((float4*)edge_feat)[(size_t)e * 32 + lane] = r;
}

// ------------- node aggregation (1 warp / node, pure gather) ----------------
__global__ void node_kernel(float* __restrict__ node_feat,
                            const float* __restrict__ edge_feat) {
    int warp = (blockIdx.x * blockDim.x + threadIdx.x) >> 5;
    int lane = threadIdx.x & 31;
    if (warp >= N_NODES) return;
    int n = warp;
    int start = g_node_off[n], end = g_node_off[n + 1];
    float4 acc = make_float4(0.f, 0.f, 0.f, 0.f);
    const float4* EF = (const float4*)edge_feat;
    for (int i = start; i < end; i++) {
        int p = g_node_pairs[i];
        int e = g_node_edges[i];
        float w = g_attn[p] * g_inv_denom[e];
        float4 ef = EF[(size_t)e * 32 + lane];
        acc.x += w * ef.x; acc.y += w * ef.y; acc.z += w * ef.z; acc.w += w * ef.w;
    }
    ((float4*)node_feat)[(size_t)n * 32 + lane] = acc;
}

// ------------------------- launch -------------------------------------------
extern "C" void kernel_launch(void* const* d_in, const int* in_sizes, int n_in,
                              void* d_out, int out_size) {
    const float* x          = (const float*)d_in[0];
    const int*   node_types = (const int*)  d_in[1];
    const int*   edge_type  = (const int*)  d_in[2];
    const int*   node_idx   = (const int*)  d_in[3];
    const int*   edge_idx   = (const int*)  d_in[4];
    const float* type_query = (const float*)d_in[5];
    const float* fc1_w      = (const float*)d_in[6];
    const float* fc1_b      = (const float*)d_in[7];
    const float* fc2_w      = (const float*)d_in[8];
    const float* fc2_b      = (const float*)d_in[9];
    const float* Wq         = (const float*)d_in[10];
    const float* Wv         = (const float*)d_in[11];
    const float* edge_ctx   = (const float*)d_in[12];

    float* node_feat = (float*)d_out;
    float* edge_feat = (float*)d_out + (size_t)N_NODES * OUT_DIM;

    prep_kernel<<<(BIGW_ROWS * IN_DIM + 3 * HID + 255) / 256, 256>>>(
        Wv, fc1_w, Wq, edge_ctx, type_query);
    prep2_kernel<<<(BIGW_ROWS * IN_DIM + 255) / 256, 256>>>();

    dim3 ggrid((N_NODES + 127) / 128, 3);
    hmma_gemm<<<ggrid, 256>>>(x);

    post_kernel<<<(N_NODES * 32 + 255) / 256, 256>>>(node_types, fc1_b, fc2_w, fc2_b);

    zero_kernel<<<(N_NODES + 255) / 256, 256>>>();
    hist_kernel<<<1024, 256>>>(edge_idx, node_idx);
    scan_kernel<<<2, 1024>>>();
    scatter_kernel<<<1024, 256>>>(edge_idx, node_idx);

    edge_kernel<<<(N_EDGES * 32 + 255) / 256, 256>>>(edge_type, edge_feat);
    node_kernel<<<(N_NODES * 32 + 255) / 256, 256>>>(node_feat, edge_feat);
}

// round 17
// speedup vs baseline: 1.9955x; 1.3271x over previous
#include <cuda_runtime.h>
#include <cuda_bf16.h>
#include <math.h>
#include <stdint.h>

#define N_NODES 100000
#define N_EDGES 50000
#define N_PAIRS 1000000
#define IN_DIM 256
#define OUT_DIM 128
#define HID 32
#define TQ_DIM 64
#define BIGW_ROWS 192
#define NEG_SLOPE 0.2f

// ------------------------- scratch (static device memory) -------------------
__device__ float g_BigW[BIGW_ROWS * IN_DIM];      // [Wv(128) | fc1_a(32) | W3(3) | pad] x 256
__device__ float g_tqW[3 * HID];
__device__ float g_V[(size_t)N_NODES * OUT_DIM];
__device__ float g_H[(size_t)N_NODES * 64];
__device__ float g_A[(size_t)N_NODES * 4];
__device__ float g_attn[N_PAIRS];
__device__ float g_inv_denom[N_EDGES];
__device__ int   g_edge_cnt[N_EDGES];
__device__ int   g_edge_off[N_EDGES + 1];
__device__ int   g_edge_cur[N_EDGES];
__device__ int   g_node_cnt[N_NODES];
__device__ int   g_node_off[N_NODES + 1];
__device__ int   g_node_cur[N_NODES];
__device__ int   g_edge_pairs[N_PAIRS];
__device__ int   g_edge_nodes[N_PAIRS];
__device__ int   g_node_pairs[N_PAIRS];
__device__ int   g_node_edges[N_PAIRS];
// bf16 hi/lo weights, plain row-major [192][256]
__device__ __nv_bfloat16 g_Whi[BIGW_ROWS * IN_DIM];
__device__ __nv_bfloat16 g_Wlo[BIGW_ROWS * IN_DIM];

// ------------------------- prep1: fused fp32 weights -------------------------
__global__ void prep_kernel(const float* __restrict__ Wv,
                            const float* __restrict__ fc1_w,
                            const float* __restrict__ Wq,
                            const float* __restrict__ edge_ctx,
                            const float* __restrict__ type_query) {
    int idx = blockIdx.x * blockDim.x + threadIdx.x;
    const int total = BIGW_ROWS * IN_DIM;
    if (idx < total) {
        int r = idx / IN_DIM, c = idx % IN_DIM;
        float v;
        if (r < 128) {
            v = Wv[r * IN_DIM + c];
        } else if (r < 160) {
            v = fc1_w[(r - 128) * (IN_DIM + TQ_DIM) + c];
        } else if (r < 163) {
            int t = r - 160;
            float s = 0.f;
            for (int j = 0; j < OUT_DIM; j++)
                s += edge_ctx[t * OUT_DIM + j] * Wq[j * IN_DIM + c];
            v = s;
        } else {
            v = 0.f;
        }
        g_BigW[idx] = v;
    } else if (idx < total + 3 * HID) {
        int e2 = idx - total;
        int t = e2 / HID, j = e2 % HID;
        float s = 0.f;
        for (int d = 0; d < TQ_DIM; d++)
            s += type_query[t * TQ_DIM + d] * fc1_w[j * (IN_DIM + TQ_DIM) + IN_DIM + d];
        g_tqW[t * HID + j] = s;
    }
}

// ------------------------- prep2: bf16 hi/lo weights -------------------------
__global__ void prep2_kernel() {
    int idx = blockIdx.x * blockDim.x + threadIdx.x;
    if (idx >= BIGW_ROWS * IN_DIM) return;
    float w = g_BigW[idx];
    __nv_bfloat16 hi = __float2bfloat16(w);
    __nv_bfloat16 lo = __float2bfloat16(w - __bfloat162float(hi));
    g_Whi[idx] = hi;
    g_Wlo[idx] = lo;
}

// ------------------------- HMMA GEMM: [V | H] = x @ BigW.T ------------------
// FUSED: one CTA computes 128 rows x all 192 cols (x read once, split once).
// 8 warps as 2M x 4N; warp tile 64x48 -> acc[4][6][4]; K chunks of 32.
#define GLDA 40   // smem row stride in halfs (32 + 8 pad)
#define SA_H 0
#define SA_L (128 * GLDA)
#define SB_H (2 * 128 * GLDA)
#define SB_L (2 * 128 * GLDA + 192 * GLDA)
#define HM_SMEM ((2 * 128 + 2 * 192) * GLDA * 2)   // 51200 bytes

__device__ __forceinline__ void mma16816(float* c, const uint32_t* a, const uint32_t* b) {
    asm volatile(
        "mma.sync.aligned.m16n8k16.row.col.f32.bf16.bf16.f32 "
        "{%0,%1,%2,%3}, {%4,%5,%6,%7}, {%8,%9}, {%0,%1,%2,%3};"
        : "+f"(c[0]), "+f"(c[1]), "+f"(c[2]), "+f"(c[3])
        : "r"(a[0]), "r"(a[1]), "r"(a[2]), "r"(a[3]), "r"(b[0]), "r"(b[1]));
}

__global__ __launch_bounds__(256) void hmma_gemm(const float* __restrict__ x) {
    extern __shared__ __nv_bfloat16 sm[];
    __nv_bfloat16* Ah = sm + SA_H;
    __nv_bfloat16* Al = sm + SA_L;
    __nv_bfloat16* Bh = sm + SB_H;
    __nv_bfloat16* Bl = sm + SB_L;

    const int tid = threadIdx.x;
    const int wid = tid >> 5, lane = tid & 31;
    const int g = lane >> 2, t = lane & 3;
    const int warp_m = wid >> 2, warp_n = wid & 3;    // 2M x 4N
    const int row0 = blockIdx.x * 128;

    float acc[4][6][4];
#pragma unroll
    for (int mt = 0; mt < 4; mt++)
#pragma unroll
        for (int nt = 0; nt < 6; nt++)
#pragma unroll
            for (int q = 0; q < 4; q++) acc[mt][nt][q] = 0.f;

    for (int k0 = 0; k0 < IN_DIM; k0 += 32) {
        // ---- A: 128 rows x 32 k-cols fp32 -> bf16 hi/lo ----
#pragma unroll
        for (int i = 0; i < 4; i++) {
            int idx = tid + i * 256;        // 0..1023
            int r = idx >> 3, c4 = idx & 7;
            float4 v = make_float4(0.f, 0.f, 0.f, 0.f);
            int gr = row0 + r;
            if (gr < N_NODES)
                v = *(const float4*)(x + (size_t)gr * IN_DIM + k0 + c4 * 4);
            __nv_bfloat16 h0 = __float2bfloat16(v.x), h1 = __float2bfloat16(v.y);
            __nv_bfloat16 h2 = __float2bfloat16(v.z), h3 = __float2bfloat16(v.w);
            __nv_bfloat16 l0 = __float2bfloat16(v.x - __bfloat162float(h0));
            __nv_bfloat16 l1 = __float2bfloat16(v.y - __bfloat162float(h1));
            __nv_bfloat16 l2 = __float2bfloat16(v.z - __bfloat162float(h2));
            __nv_bfloat16 l3 = __float2bfloat16(v.w - __bfloat162float(h3));
            int base = r * GLDA + c4 * 4;
            __nv_bfloat162 p;
            p.x = h0; p.y = h1; *(__nv_bfloat162*)&Ah[base]     = p;
            p.x = h2; p.y = h3; *(__nv_bfloat162*)&Ah[base + 2] = p;
            p.x = l0; p.y = l1; *(__nv_bfloat162*)&Al[base]     = p;
            p.x = l2; p.y = l3; *(__nv_bfloat162*)&Al[base + 2] = p;
        }
        // ---- B: 192 rows x 32 k-cols bf16 hi/lo, uint4 copies (3/thread) ----
#pragma unroll
        for (int j = 0; j < 3; j++) {
            int idx = tid + j * 256;        // 0..767
            int r = idx >> 2, c8 = idx & 3;
            *(uint4*)&Bh[r * GLDA + c8 * 8] =
                *(const uint4*)(g_Whi + (size_t)r * IN_DIM + k0 + c8 * 8);
            *(uint4*)&Bl[r * GLDA + c8 * 8] =
                *(const uint4*)(g_Wlo + (size_t)r * IN_DIM + k0 + c8 * 8);
        }
        __syncthreads();

#pragma unroll
        for (int ks = 0; ks < 2; ks++) {
            int kb = ks * 16;
            uint32_t ah[4][4], al[4][4];
#pragma unroll
            for (int mt = 0; mt < 4; mt++) {
                int rb = warp_m * 64 + mt * 16;
                ah[mt][0] = *(uint32_t*)&Ah[(rb + g) * GLDA + kb + 2 * t];
                ah[mt][1] = *(uint32_t*)&Ah[(rb + g + 8) * GLDA + kb + 2 * t];
                ah[mt][2] = *(uint32_t*)&Ah[(rb + g) * GLDA + kb + 2 * t + 8];
                ah[mt][3] = *(uint32_t*)&Ah[(rb + g + 8) * GLDA + kb + 2 * t + 8];
                al[mt][0] = *(uint32_t*)&Al[(rb + g) * GLDA + kb + 2 * t];
                al[mt][1] = *(uint32_t*)&Al[(rb + g + 8) * GLDA + kb + 2 * t];
                al[mt][2] = *(uint32_t*)&Al[(rb + g) * GLDA + kb + 2 * t + 8];
                al[mt][3] = *(uint32_t*)&Al[(rb + g + 8) * GLDA + kb + 2 * t + 8];
            }
#pragma unroll
            for (int nt = 0; nt < 6; nt++) {
                int nb = warp_n * 48 + nt * 8;
                uint32_t bh[2], bl[2];
                bh[0] = *(uint32_t*)&Bh[(nb + g) * GLDA + kb + 2 * t];
                bh[1] = *(uint32_t*)&Bh[(nb + g) * GLDA + kb + 2 * t + 8];
                bl[0] = *(uint32_t*)&Bl[(nb + g) * GLDA + kb + 2 * t];
                bl[1] = *(uint32_t*)&Bl[(nb + g) * GLDA + kb + 2 * t + 8];
#pragma unroll
                for (int mt = 0; mt < 4; mt++) {
                    mma16816(acc[mt][nt], ah[mt], bh);
                    mma16816(acc[mt][nt], al[mt], bh);
                    mma16816(acc[mt][nt], ah[mt], bl);
                }
            }
        }
        __syncthreads();
    }

    // ---- epilogue ----
#pragma unroll
    for (int mt = 0; mt < 4; mt++) {
#pragma unroll
        for (int half = 0; half < 2; half++) {
            int lr = warp_m * 64 + mt * 16 + g + half * 8;
            int gr = row0 + lr;
            if (gr >= N_NODES) continue;
#pragma unroll
            for (int nt = 0; nt < 6; nt++) {
                int nb = warp_n * 48 + nt * 8;
                int col = nb + 2 * t;
                float2 v;
                v.x = acc[mt][nt][half * 2 + 0];
                v.y = acc[mt][nt][half * 2 + 1];
                if (nb < 128)
                    *(float2*)(g_V + (size_t)gr * OUT_DIM + col) = v;
                else
                    *(float2*)(g_H + (size_t)gr * 64 + (col - 128)) = v;
            }
        }
    }
}

// ------------------------- per-node gates: A[n][t] --------------------------
__global__ void post_kernel(const int* __restrict__ node_types,
                            const float* __restrict__ fc1_b,
                            const float* __restrict__ fc2_w,
                            const float* __restrict__ fc2_b) {
    int warp = (blockIdx.x * blockDim.x + threadIdx.x) >> 5;
    int lane = threadIdx.x & 31;
    if (warp >= N_NODES) return;
    int n = warp;
    int t = node_types[n];
    float h = tanhf(g_H[(size_t)n * 64 + lane] + g_tqW[t * HID + lane] + fc1_b[lane]);
    float c = h * fc2_w[lane];
#pragma unroll
    for (int d = 16; d; d >>= 1) c += __shfl_xor_sync(0xffffffffu, c, d);
    float at = 1.f / (1.f + __expf(-(c + fc2_b[0])));
    if (lane < 3) {
        float s = g_H[(size_t)n * 64 + 32 + lane];
        s = s >= 0.f ? s : NEG_SLOPE * s;
        g_A[(size_t)n * 4 + lane] = s * at;
    }
}

// ------------------------- CSR build ----------------------------------------
__global__ void zero_kernel() {
    int i = blockIdx.x * blockDim.x + threadIdx.x;
    if (i < N_EDGES) g_edge_cnt[i] = 0;
    if (i < N_NODES) g_node_cnt[i] = 0;
}

__global__ void hist_kernel(const int* __restrict__ edge_idx,
                            const int* __restrict__ node_idx) {
    int stride = gridDim.x * blockDim.x;
    for (int p = blockIdx.x * blockDim.x + threadIdx.x; p < N_PAIRS; p += stride) {
        int e = edge_idx[p];
        int n = node_idx[p];
        atomicAdd(&g_edge_cnt[e], 1);
        atomicAdd(&g_node_cnt[n], 1);
    }
}

__global__ void scan_kernel() {
    int n;
    int *cnt, *off, *cur;
    if (blockIdx.x == 0) { n = N_EDGES; cnt = g_edge_cnt; off = g_edge_off; cur = g_edge_cur; }
    else                 { n = N_NODES; cnt = g_node_cnt; off = g_node_off; cur = g_node_cur; }
    __shared__ int wsum[32];
    __shared__ int s_total;
    __shared__ int s_carry;
    int tid = threadIdx.x, lane = tid & 31, wid = tid >> 5;
    if (tid == 0) s_carry = 0;
    __syncthreads();
    for (int base = 0; base < n; base += 1024) {
        int i = base + tid;
        int v = (i < n) ? cnt[i] : 0;
        int incl = v;
#pragma unroll
        for (int d = 1; d < 32; d <<= 1) {
            int y = __shfl_up_sync(0xffffffffu, incl, d);
            if (lane >= d) incl += y;
        }
        if (lane == 31) wsum[wid] = incl;
        __syncthreads();
        if (wid == 0) {
            int s = wsum[lane];
            int si = s;
#pragma unroll
            for (int d = 1; d < 32; d <<= 1) {
                int y = __shfl_up_sync(0xffffffffu, si, d);
                if (lane >= d) si += y;
            }
            wsum[lane] = si - s;
            if (lane == 31) s_total = si;
        }
        __syncthreads();
        int excl = s_carry + wsum[wid] + incl - v;
        if (i < n) { off[i] = excl; cur[i] = excl; }
        __syncthreads();
        if (tid == 0) s_carry += s_total;
        __syncthreads();
    }
    if (threadIdx.x == 0) off[n] = s_carry;
}

__global__ void scatter_kernel(const int* __restrict__ edge_idx,
                               const int* __restrict__ node_idx) {
    int stride = gridDim.x * blockDim.x;
    for (int p = blockIdx.x * blockDim.x + threadIdx.x; p < N_PAIRS; p += stride) {
        int e = edge_idx[p];
        int n = node_idx[p];
        int pos = atomicAdd(&g_edge_cur[e], 1);
        g_edge_pairs[pos] = p;
        g_edge_nodes[pos] = n;
        int pos2 = atomicAdd(&g_node_cur[n], 1);
        g_node_pairs[pos2] = p;
        g_node_edges[pos2] = e;
    }
}

// ------------- segment softmax + edge aggregation (1 warp / edge) ----------
__global__ void edge_kernel(const int* __restrict__ edge_type,
                            float* __restrict__ edge_feat) {
    int warp = (blockIdx.x * blockDim.x + threadIdx.x) >> 5;
    int lane = threadIdx.x & 31;
    if (warp >= N_EDGES) return;
    int e = warp;
    int start = g_edge_off[e], end = g_edge_off[e + 1];
    int cnt = end - start;
    int et = edge_type[e];
    const float4* Vb = (const float4*)g_V;
    float4 acc = make_float4(0.f, 0.f, 0.f, 0.f);
    float inv;

    if (cnt <= 32) {
        bool valid = lane < cnt;
        int p = 0, n = 0;
        float a = -3.4e38f;
        if (valid) {
            p = g_edge_pairs[start + lane];
            n = g_edge_nodes[start + lane];
            a = g_A[(size_t)n * 4 + et];
        }
        float m = a;
#pragma unroll
        for (int d = 16; d; d >>= 1) m = fmaxf(m, __shfl_xor_sync(0xffffffffu, m, d));
        float ea = valid ? __expf(a - m) : 0.f;
        float s = ea;
#pragma unroll
        for (int d = 16; d; d >>= 1) s += __shfl_xor_sync(0xffffffffu, s, d);
        inv = (s > 0.f) ? 1.f / s : 0.f;
        if (valid) g_attn[p] = ea;
        for (int j = 0; j < cnt; j++) {
            float w = __shfl_sync(0xffffffffu, ea, j);
            int  nn = __shfl_sync(0xffffffffu, n, j);
            float4 v = Vb[(size_t)nn * 32 + lane];
            acc.x += w * v.x; acc.y += w * v.y; acc.z += w * v.z; acc.w += w * v.w;
        }
    } else {
        float m = -3.4e38f;
        for (int i = start + lane; i < end; i += 32) {
            int n = g_edge_nodes[i];
            float a = g_A[(size_t)n * 4 + et];
            g_attn[g_edge_pairs[i]] = a;
            m = fmaxf(m, a);
        }
#pragma unroll
        for (int d = 16; d; d >>= 1) m = fmaxf(m, __shfl_xor_sync(0xffffffffu, m, d));
        float s = 0.f;
        for (int i = start + lane; i < end; i += 32) {
            int p = g_edge_pairs[i];
            float ea = __expf(g_attn[p] - m);
            g_attn[p] = ea;
            s += ea;
        }
#pragma unroll
        for (int d = 16; d; d >>= 1) s += __shfl_xor_sync(0xffffffffu, s, d);
        inv = (s > 0.f) ? 1.f / s : 0.f;
        __syncwarp();
        for (int i = start; i < end; i++) {
            float w = g_attn[g_edge_pairs[i]];
            int n = g_edge_nodes[i];
            float4 v = Vb[(size_t)n * 32 + lane];
            acc.x += w * v.x; acc.y += w * v.y; acc.z += w * v.z; acc.w += w * v.w;
        }
    }
    if (lane == 0) g_inv_denom[e] = inv;
    float4 r = make_float4(acc.x * inv, acc.y * inv, acc.z * inv, acc.w * inv);
    ((float4*)edge_feat)[(size_t)e * 32 + lane] = r;
}

// ------------- node aggregation (1 warp / node, pure gather) ----------------
__global__ void node_kernel(float* __restrict__ node_feat,
                            const float* __restrict__ edge_feat) {
    int warp = (blockIdx.x * blockDim.x + threadIdx.x) >> 5;
    int lane = threadIdx.x & 31;
    if (warp >= N_NODES) return;
    int n = warp;
    int start = g_node_off[n], end = g_node_off[n + 1];
    float4 acc = make_float4(0.f, 0.f, 0.f, 0.f);
    const float4* EF = (const float4*)edge_feat;
    for (int i = start; i < end; i++) {
        int p = g_node_pairs[i];
        int e = g_node_edges[i];
        float w = g_attn[p] * g_inv_denom[e];
        float4 ef = EF[(size_t)e * 32 + lane];
        acc.x += w * ef.x; acc.y += w * ef.y; acc.z += w * ef.z; acc.w += w * ef.w;
    }
    ((float4*)node_feat)[(size_t)n * 32 + lane] = acc;
}

// ------------------------- launch -------------------------------------------
extern "C" void kernel_launch(void* const* d_in, const int* in_sizes, int n_in,
                              void* d_out, int out_size) {
    const float* x          = (const float*)d_in[0];
    const int*   node_types = (const int*)  d_in[1];
    const int*   edge_type  = (const int*)  d_in[2];
    const int*   node_idx   = (const int*)  d_in[3];
    const int*   edge_idx   = (const int*)  d_in[4];
    const float* type_query = (const float*)d_in[5];
    const float* fc1_w      = (const float*)d_in[6];
    const float* fc1_b      = (const float*)d_in[7];
    const float* fc2_w      = (const float*)d_in[8];
    const float* fc2_b      = (const float*)d_in[9];
    const float* Wq         = (const float*)d_in[10];
    const float* Wv         = (const float*)d_in[11];
    const float* edge_ctx   = (const float*)d_in[12];

    float* node_feat = (float*)d_out;
    float* edge_feat = (float*)d_out + (size_t)N_NODES * OUT_DIM;

    cudaFuncSetAttribute(hmma_gemm, cudaFuncAttributeMaxDynamicSharedMemorySize, HM_SMEM);

    // order chosen so hmma_gemm sits in the ncu capture slot (4th launch)
    zero_kernel<<<(N_NODES + 255) / 256, 256>>>();
    prep_kernel<<<(BIGW_ROWS * IN_DIM + 3 * HID + 255) / 256, 256>>>(
        Wv, fc1_w, Wq, edge_ctx, type_query);
    prep2_kernel<<<(BIGW_ROWS * IN_DIM + 255) / 256, 256>>>();

    hmma_gemm<<<(N_NODES + 127) / 128, 256, HM_SMEM>>>(x);

    hist_kernel<<<1024, 256>>>(edge_idx, node_idx);
    scan_kernel<<<2, 1024>>>();
    scatter_kernel<<<1024, 256>>>(edge_idx, node_idx);

    post_kernel<<<(N_NODES * 32 + 255) / 256, 256>>>(node_types, fc1_b, fc2_w, fc2_b);

    edge_kernel<<<(N_EDGES * 32 + 255) / 256, 256>>>(edge_type, edge_feat);
    node_kernel<<<(N_NODES * 32 + 255) / 256, 256>>>(node_feat, edge_feat);
}